// round 5
// baseline (speedup 1.0000x reference)
#include <cuda_runtime.h>
#include <cstdint>

// out[b,k,oc,x] = sum_ci W[k,oc,ci]*in[b,ci,k,x] + bias[k,oc]
// in: [4096,128,9,9]  w: [9,128,128]  bias: [9,128]  out: [4096,9,128,9] (f32)
//
// Per k: D[oc,n] = sum_ci W[oc,ci]*X[n,ci], n=b*9+x. tf32 mma.sync (m16n8k8),
// inputs rounded with cvt.rna.tf32.f32 at staging (symmetric error, ~3-4e-4 norm).
// CTA tile: M=128, N=144 (=16 batches), K=128. grid=(9,256), 8 warps (4M x 2N).

#define KK     9
#define CIN    128
#define COUT   128
#define NB     16
#define NTILE  144
#define NTHR   256

#define SWS 132                         // sW word stride: A-frag banks (4g+t) perfect
#define SXS 168                         // sX word stride: >=144, 168%32==8 -> B-frag banks (8t+g) perfect
#define SDS 168                         // sD word stride (even -> aligned float2 stores)
#define SW_BYTES (128 * SWS * 4)        // 67584
#define SX_BYTES (128 * SXS * 4)        // 86016
#define SM_BIAS  (SW_BYTES + SX_BYTES)  // 153600
#define SMEM_BYTES (SM_BIAS + 512)      // 154112 -> 1 CTA/SM

__device__ __forceinline__ uint32_t f2tf32(float f) {
    uint32_t u;
    asm("cvt.rna.tf32.f32 %0, %1;" : "=r"(u) : "f"(f));
    return u;
}

__device__ __forceinline__ void mma_tf32(float* d, const uint32_t* a, const uint32_t* b) {
    asm volatile(
        "mma.sync.aligned.m16n8k8.row.col.f32.tf32.tf32.f32 "
        "{%0,%1,%2,%3}, {%4,%5,%6,%7}, {%8,%9}, {%0,%1,%2,%3};"
        : "+f"(d[0]), "+f"(d[1]), "+f"(d[2]), "+f"(d[3])
        : "r"(a[0]), "r"(a[1]), "r"(a[2]), "r"(a[3]), "r"(b[0]), "r"(b[1]));
}

__global__ void __launch_bounds__(NTHR, 1)
gather_vertical_tf32(const float* __restrict__ in,
                     const float* __restrict__ w,
                     const float* __restrict__ bias,
                     float* __restrict__ out)
{
    extern __shared__ char smem[];
    uint32_t* sW = reinterpret_cast<uint32_t*>(smem);             // [oc][ci] stride SWS (tf32 bits)
    uint32_t* sX = reinterpret_cast<uint32_t*>(smem + SW_BYTES);  // [ci][n]  stride SXS (tf32 bits)
    float*    sD = reinterpret_cast<float*>(smem);                // epilogue staging [oc][n] stride SDS
    float*    sBias = reinterpret_cast<float*>(smem + SM_BIAS);

    const int tid = threadIdx.x;
    const int k   = blockIdx.x;
    const int b0  = blockIdx.y * NB;

    // ---- stage bias ----
    if (tid < COUT) sBias[tid] = bias[k * COUT + tid];

    // ---- stage W[k]: [oc][ci] coalesced LDG -> cvt.rna -> STS ----
    {
        const float* wk = w + k * COUT * CIN;
        #pragma unroll 4
        for (int i = tid; i < COUT * CIN; i += NTHR) {
            int oc = i >> 7, ci = i & 127;
            sW[oc * SWS + ci] = f2tf32(wk[i]);
        }
    }

    // ---- stage X: in[b0..b0+15, :, k, 0..8] -> sX[ci][n], n = bl*9+x (max 143 < SXS) ----
    {
        const float* inb = in + (size_t)b0 * (CIN * 81) + k * 9;
        #pragma unroll 4
        for (int i = tid; i < NB * CIN * 9; i += NTHR) {
            int x = i % 9;
            int p = i / 9;                 // p = bl*128 + ci
            int ci = p & 127, bl = p >> 7;
            sX[ci * SXS + bl * 9 + x] = f2tf32(inb[(size_t)p * 81 + x]);
        }
    }
    __syncthreads();

    // ---- warp tiling: 4 warps along M (32 oc), 2 along N (72 n) ----
    const int wid  = tid >> 5, lane = tid & 31;
    const int g    = lane >> 2, t = lane & 3;
    const int oc0  = (wid & 3) * 32;
    const int n0   = (wid >> 2) * 72;

    float d[2][9][4];
    #pragma unroll
    for (int mt = 0; mt < 2; mt++)
        #pragma unroll
        for (int nt = 0; nt < 9; nt++)
            #pragma unroll
            for (int j = 0; j < 4; j++) d[mt][nt][j] = 0.0f;

    #pragma unroll 4
    for (int ks = 0; ks < 16; ks++) {
        const int ci0 = ks * 8;

        uint32_t a[2][4];
        #pragma unroll
        for (int mt = 0; mt < 2; mt++) {
            int r = oc0 + mt * 16 + g;
            a[mt][0] = sW[r * SWS + ci0 + t];
            a[mt][1] = sW[(r + 8) * SWS + ci0 + t];
            a[mt][2] = sW[r * SWS + ci0 + t + 4];
            a[mt][3] = sW[(r + 8) * SWS + ci0 + t + 4];
        }

        uint32_t b[9][2];
        #pragma unroll
        for (int nt = 0; nt < 9; nt++) {
            int n = n0 + nt * 8 + g;
            b[nt][0] = sX[(ci0 + t) * SXS + n];
            b[nt][1] = sX[(ci0 + t + 4) * SXS + n];
        }

        #pragma unroll
        for (int mt = 0; mt < 2; mt++)
            #pragma unroll
            for (int nt = 0; nt < 9; nt++)
                mma_tf32(d[mt][nt], a[mt], b[nt]);
    }

    __syncthreads();   // all warps done reading sW/sX; reuse region as sD

    // ---- D frags (+bias) -> sD[oc][n] ----
    #pragma unroll
    for (int mt = 0; mt < 2; mt++) {
        int r0 = oc0 + mt * 16 + g;
        int r1 = r0 + 8;
        float bv0 = sBias[r0], bv1 = sBias[r1];
        #pragma unroll
        for (int nt = 0; nt < 9; nt++) {
            int n = n0 + nt * 8 + 2 * t;
            *reinterpret_cast<float2*>(sD + r0 * SDS + n) =
                make_float2(d[mt][nt][0] + bv0, d[mt][nt][1] + bv0);
            *reinterpret_cast<float2*>(sD + r1 * SDS + n) =
                make_float2(d[mt][nt][2] + bv1, d[mt][nt][3] + bv1);
        }
    }
    __syncthreads();

    // ---- coalesced store: 16 contiguous 1152-float blocks ----
    {
        float* ob = out + (size_t)b0 * (9 * COUT * 9) + (size_t)k * (COUT * 9);
        #pragma unroll 4
        for (int i = tid; i < NB * 1152; i += NTHR) {
            int bl = i / 1152;
            int r  = i - bl * 1152;        // r = oc*9 + x
            int oc = r / 9;
            int x  = r - 9 * oc;
            ob[(size_t)bl * (9 * COUT * 9) + r] = sD[oc * SDS + bl * 9 + x];
        }
    }
}

extern "C" void kernel_launch(void* const* d_in, const int* in_sizes, int n_in,
                              void* d_out, int out_size)
{
    const float* in   = (const float*)d_in[0];
    const float* w    = (const float*)d_in[1];
    const float* bias = (const float*)d_in[2];
    float* out        = (float*)d_out;

    int B = in_sizes[0] / (CIN * 81);    // 4096

    cudaFuncSetAttribute(gather_vertical_tf32,
                         cudaFuncAttributeMaxDynamicSharedMemorySize, SMEM_BYTES);

    dim3 grid(KK, B / NB);
    gather_vertical_tf32<<<grid, NTHR, SMEM_BYTES>>>(in, w, bias, out);
}

// round 6
// speedup vs baseline: 1.2586x; 1.2586x over previous
#include <cuda_runtime.h>
#include <cstdint>

// out[b,k,oc,x] = sum_ci W[k,oc,ci]*in[b,ci,k,x] + bias[k,oc]
// in: [4096,128,9,9]  w: [9,128,128]  bias: [9,128]  out: [4096,9,128,9] (f32)
//
// Per k: D[oc,n] = sum_ci W[oc,ci]*X[n,ci], n=b*9+x. tf32 mma.sync m16n8k8,
// cvt.rna at staging. CTA tile M=128, N=72 (8 batches), K=128.
// 8 warps along M (16 oc each), warp tile 16x72 (9 n-frags). 2 CTAs/SM.

#define KK     9
#define CIN    128
#define COUT   128
#define NB     8
#define NTILE  72
#define NTHR   256

#define SWS 132                         // sW stride: A-frag banks (4g+t) perfect
#define SXS 88                          // sX stride: 88%32=24 -> B-frag banks (24t+8nt+g) perfect
#define SDS 76                          // sD stride (even, >=72)
#define SW_BYTES (128 * SWS * 4)        // 67584
#define SX_BYTES (128 * SXS * 4)        // 45056
#define SM_BIAS  (SW_BYTES + SX_BYTES)  // 112640
#define SMEM_BYTES (SM_BIAS + 512)      // 113152 -> 2 CTAs/SM

__device__ __forceinline__ uint32_t f2tf32(float f) {
    uint32_t u;
    asm("cvt.rna.tf32.f32 %0, %1;" : "=r"(u) : "f"(f));
    return u;
}

__device__ __forceinline__ void mma_tf32(float* d, const uint32_t* a, const uint32_t* b) {
    asm volatile(
        "mma.sync.aligned.m16n8k8.row.col.f32.tf32.tf32.f32 "
        "{%0,%1,%2,%3}, {%4,%5,%6,%7}, {%8,%9}, {%0,%1,%2,%3};"
        : "+f"(d[0]), "+f"(d[1]), "+f"(d[2]), "+f"(d[3])
        : "r"(a[0]), "r"(a[1]), "r"(a[2]), "r"(a[3]), "r"(b[0]), "r"(b[1]));
}

__global__ void __launch_bounds__(NTHR, 2)
gather_vertical_tf32(const float* __restrict__ in,
                     const float* __restrict__ w,
                     const float* __restrict__ bias,
                     float* __restrict__ out)
{
    extern __shared__ char smem[];
    uint32_t* sW = reinterpret_cast<uint32_t*>(smem);             // [oc][ci] tf32 bits, stride SWS
    uint32_t* sX = reinterpret_cast<uint32_t*>(smem + SW_BYTES);  // [ci][n]  tf32 bits, stride SXS
    float*    sD = reinterpret_cast<float*>(smem);                // epilogue [oc][n], stride SDS
    float*    sBias = reinterpret_cast<float*>(smem + SM_BIAS);

    const int tid = threadIdx.x;
    const int k   = blockIdx.x;
    const int b0  = blockIdx.y * NB;

    if (tid < COUT) sBias[tid] = bias[k * COUT + tid];

    // ---- stage W[k]: coalesced LDG -> cvt.rna -> STS ----
    {
        const float* wk = w + k * COUT * CIN;
        #pragma unroll 4
        for (int i = tid; i < COUT * CIN; i += NTHR) {
            int oc = i >> 7, ci = i & 127;
            sW[oc * SWS + ci] = f2tf32(wk[i]);
        }
    }

    // ---- stage X: in[b0..b0+7, :, k, 0..8] -> sX[ci][bl*9+x] ----
    {
        const float* inb = in + (size_t)b0 * (CIN * 81) + k * 9;
        #pragma unroll 4
        for (int i = tid; i < NB * CIN * 9; i += NTHR) {
            int x = i % 9;
            int p = i / 9;                  // p = bl*128 + ci
            int ci = p & 127, bl = p >> 7;
            sX[ci * SXS + bl * 9 + x] = f2tf32(inb[(size_t)p * 81 + x]);
        }
    }
    __syncthreads();

    // ---- warp tile: 16 oc x 72 n ----
    const int wid  = tid >> 5, lane = tid & 31;
    const int g    = lane >> 2, t = lane & 3;
    const int oc0  = wid * 16;

    float d[9][4];
    #pragma unroll
    for (int nt = 0; nt < 9; nt++)
        #pragma unroll
        for (int j = 0; j < 4; j++) d[nt][j] = 0.0f;

    // pointer-increment addressing (cuts alu in the hot loop)
    const uint32_t* pa0 = sW + (oc0 + g) * SWS + t;         // row g
    const uint32_t* pa1 = sW + (oc0 + g + 8) * SWS + t;     // row g+8
    const uint32_t* pb  = sX + t * SXS + g;                 // ci rows t / t+4

    #pragma unroll 4
    for (int ks = 0; ks < 16; ks++) {
        uint32_t a[4];
        a[0] = pa0[0];
        a[1] = pa1[0];
        a[2] = pa0[4];
        a[3] = pa1[4];

        uint32_t b[9][2];
        #pragma unroll
        for (int nt = 0; nt < 9; nt++) {
            b[nt][0] = pb[nt * 8];
            b[nt][1] = pb[4 * SXS + nt * 8];
        }

        #pragma unroll
        for (int nt = 0; nt < 9; nt++)
            mma_tf32(d[nt], a, b[nt]);

        pa0 += 8; pa1 += 8; pb += 8 * SXS;
    }

    __syncthreads();   // done reading sW/sX; reuse region as sD

    // ---- D frags (+bias) -> sD[oc][n] ----
    {
        int r0 = oc0 + g;
        int r1 = r0 + 8;
        float bv0 = sBias[r0], bv1 = sBias[r1];
        #pragma unroll
        for (int nt = 0; nt < 9; nt++) {
            int n = nt * 8 + 2 * t;
            *reinterpret_cast<float2*>(sD + r0 * SDS + n) =
                make_float2(d[nt][0] + bv0, d[nt][1] + bv0);
            *reinterpret_cast<float2*>(sD + r1 * SDS + n) =
                make_float2(d[nt][2] + bv1, d[nt][3] + bv1);
        }
    }
    __syncthreads();

    // ---- coalesced store: 8 contiguous 1152-float blocks ----
    {
        float* ob = out + (size_t)b0 * (9 * COUT * 9) + (size_t)k * (COUT * 9);
        #pragma unroll 4
        for (int i = tid; i < NB * 1152; i += NTHR) {
            int bl = i / 1152;
            int r  = i - bl * 1152;         // r = oc*9 + x
            int oc = r / 9;
            int x  = r - 9 * oc;
            ob[(size_t)bl * (9 * COUT * 9) + r] = sD[oc * SDS + bl * 9 + x];
        }
    }
}

extern "C" void kernel_launch(void* const* d_in, const int* in_sizes, int n_in,
                              void* d_out, int out_size)
{
    const float* in   = (const float*)d_in[0];
    const float* w    = (const float*)d_in[1];
    const float* bias = (const float*)d_in[2];
    float* out        = (float*)d_out;

    int B = in_sizes[0] / (CIN * 81);    // 4096

    cudaFuncSetAttribute(gather_vertical_tf32,
                         cudaFuncAttributeMaxDynamicSharedMemorySize, SMEM_BYTES);

    dim3 grid(KK, B / NB);
    gather_vertical_tf32<<<grid, NTHR, SMEM_BYTES>>>(in, w, bias, out);
}

// round 7
// speedup vs baseline: 1.3982x; 1.1109x over previous
#include <cuda_runtime.h>
#include <cstdint>

// out[b,k,oc,x] = sum_ci W[k,oc,ci]*in[b,ci,k,x] + bias[k,oc]
// in: [4096,128,9,9]  w: [9,128,128]  bias: [9,128]  out: [4096,9,128,9] (f32)
//
// Warp-specialized tf32 mma.sync pipeline:
//   8 consumer warps: 16x72 warp tile (M=128 oc, N=72 = 8 batches), K=128
//   4 producer warps: LDG -> cvt.rna.tf32 -> STS, double-buffered at half-K (64 ci)
// W staged once per CTA, reused over 16 tiles. grid=(9,32) -> 1 wave @ 2 CTA/SM.

#define KK     9
#define CIN    128
#define COUT   128
#define NB     8
#define TILES  16
#define NTHR   384
#define NCONS  256          // consumer threads (warps 0..7)

#define SWS 132             // sW stride: A-frag banks (4g+t) perfect
#define SXS 72              // half-buffer stride: B-frag banks (8t+8nt+g) perfect
#define XH_WORDS (64 * SXS)             // 4608 words per half (18432 B)
#define SW_BYTES (128 * SWS * 4)        // 67584
#define SMEM_BYTES (SW_BYTES + 2 * XH_WORDS * 4)   // 104448 -> 2 CTAs/SM

// named barriers: full[h] = 1+h, empty[h] = 3+h
#define BAR_ARRIVE(id) asm volatile("bar.arrive %0, %1;" :: "r"(id), "r"(NTHR) : "memory")
#define BAR_SYNC(id)   asm volatile("bar.sync %0, %1;"   :: "r"(id), "r"(NTHR) : "memory")

__device__ __forceinline__ uint32_t f2tf32(float f) {
    uint32_t u;
    asm("cvt.rna.tf32.f32 %0, %1;" : "=r"(u) : "f"(f));
    return u;
}

__device__ __forceinline__ void mma_tf32(float* d, const uint32_t* a, const uint32_t* b) {
    asm volatile(
        "mma.sync.aligned.m16n8k8.row.col.f32.tf32.tf32.f32 "
        "{%0,%1,%2,%3}, {%4,%5,%6,%7}, {%8,%9}, {%0,%1,%2,%3};"
        : "+f"(d[0]), "+f"(d[1]), "+f"(d[2]), "+f"(d[3])
        : "r"(a[0]), "r"(a[1]), "r"(a[2]), "r"(a[3]), "r"(b[0]), "r"(b[1]));
}

__global__ void __launch_bounds__(NTHR, 2)
gather_vertical_ws(const float* __restrict__ in,
                   const float* __restrict__ w,
                   const float* __restrict__ bias,
                   float* __restrict__ out)
{
    extern __shared__ char smem[];
    uint32_t* sW = reinterpret_cast<uint32_t*>(smem);             // [oc][ci], stride SWS
    uint32_t* sX = reinterpret_cast<uint32_t*>(smem + SW_BYTES);  // two halves [64][72]

    const int tid = threadIdx.x;
    const int k   = blockIdx.x;
    const int yid = blockIdx.y;
    const int bbase = yid * TILES * NB;              // first batch of this CTA

    // ---- stage W[k] once (all 384 threads) ----
    {
        const float* wk = w + k * COUT * CIN;
        #pragma unroll 4
        for (int i = tid; i < COUT * CIN; i += NTHR) {
            int oc = i >> 7, ci = i & 127;
            sW[oc * SWS + ci] = f2tf32(wk[i]);
        }
    }
    __syncthreads();

    if (tid >= NCONS) {
        // =================== PRODUCER (4 warps, 128 threads) ===================
        const int ptid = tid - NCONS;
        // src base for this CTA: in[bbase][0][k][0]
        const float* src = in + (size_t)bbase * (CIN * 81) + (size_t)k * 9;

        for (int s = 0; s < 2 * TILES; s++) {
            const int h = s & 1;
            const int t = s >> 1;
            if (s >= 2) BAR_SYNC(3 + h);             // wait consumers done with buf h

            uint32_t* dst = sX + h * XH_WORDS;
            const float* st = src + (size_t)(t * NB) * (CIN * 81) + h * 64 * 81;
            #pragma unroll 4
            for (int j = 0; j < 36; j++) {
                int e  = ptid + 128 * j;             // 0..4607
                int q  = e / 9;                      // bl*64 + ci_l
                int x  = e - 9 * q;
                int bl = q >> 6;
                int ci = q & 63;
                float v = st[(size_t)(bl * CIN + ci) * 81 + x];
                dst[ci * SXS + bl * 9 + x] = f2tf32(v);
            }
            asm volatile("fence.acq_rel.cta;" ::: "memory");
            BAR_ARRIVE(1 + h);                       // signal buf h full
        }
    } else {
        // =================== CONSUMER (8 warps, 256 threads) ===================
        const int wid  = tid >> 5, lane = tid & 31;
        const int g    = lane >> 2, tl = lane & 3;
        const int oc0  = wid * 16;
        const int r0   = oc0 + g, r1 = r0 + 8;
        const float bv0 = bias[k * COUT + r0];
        const float bv1 = bias[k * COUT + r1];

        for (int t = 0; t < TILES; t++) {
            float d[9][4];
            #pragma unroll
            for (int nt = 0; nt < 9; nt++)
                #pragma unroll
                for (int j = 0; j < 4; j++) d[nt][j] = 0.0f;

            #pragma unroll
            for (int h = 0; h < 2; h++) {
                BAR_SYNC(1 + h);                     // wait buf h full

                const uint32_t* pa0 = sW + r0 * SWS + h * 64 + tl;
                const uint32_t* pa1 = sW + r1 * SWS + h * 64 + tl;
                const uint32_t* pb  = sX + h * XH_WORDS + tl * SXS + g;

                #pragma unroll
                for (int ks = 0; ks < 8; ks++) {
                    uint32_t a[4];
                    a[0] = pa0[0];
                    a[1] = pa1[0];
                    a[2] = pa0[4];
                    a[3] = pa1[4];

                    uint32_t b[9][2];
                    #pragma unroll
                    for (int nt = 0; nt < 9; nt++) {
                        b[nt][0] = pb[nt * 8];
                        b[nt][1] = pb[4 * SXS + nt * 8];
                    }
                    #pragma unroll
                    for (int nt = 0; nt < 9; nt++)
                        mma_tf32(d[nt], a, b[nt]);

                    pa0 += 8; pa1 += 8; pb += 8 * SXS;
                }
                BAR_ARRIVE(3 + h);                   // release buf h
            }

            // ---- epilogue: direct scalar STG (overlaps next tile's producer fill) ----
            float* ob = out + ((size_t)(bbase + t * NB) * 9 + k) * 1152;
            #pragma unroll
            for (int nt = 0; nt < 9; nt++) {
                int n  = nt * 8 + 2 * tl;
                int b0q = n / 9,      x0 = n - 9 * b0q;
                int b1q = (n + 1) / 9, x1 = (n + 1) - 9 * b1q;
                float* c0 = ob + (size_t)b0q * 10368;
                float* c1 = ob + (size_t)b1q * 10368;
                c0[r0 * 9 + x0] = d[nt][0] + bv0;
                c1[r0 * 9 + x1] = d[nt][1] + bv0;
                c0[r1 * 9 + x0] = d[nt][2] + bv1;
                c1[r1 * 9 + x1] = d[nt][3] + bv1;
            }
        }
    }
}

extern "C" void kernel_launch(void* const* d_in, const int* in_sizes, int n_in,
                              void* d_out, int out_size)
{
    const float* in   = (const float*)d_in[0];
    const float* w    = (const float*)d_in[1];
    const float* bias = (const float*)d_in[2];
    float* out        = (float*)d_out;

    int B = in_sizes[0] / (CIN * 81);        // 4096

    cudaFuncSetAttribute(gather_vertical_ws,
                         cudaFuncAttributeMaxDynamicSharedMemorySize, SMEM_BYTES);

    dim3 grid(KK, B / (NB * TILES));         // (9, 32)
    gather_vertical_ws<<<grid, NTHR, SMEM_BYTES>>>(in, w, bias, out);
}

// round 8
// speedup vs baseline: 1.7858x; 1.2773x over previous
#include <cuda_runtime.h>
#include <cstdint>

// out[b,k,oc,x] = sum_ci W[k,oc,ci]*in[b,ci,k,x] + bias[k,oc]
// in: [4096,128,9,9]  w: [9,128,128]  bias: [9,128]  out: [4096,9,128,9] (f32)
//
// Warp-specialized tf32 mma.sync pipeline:
//   8 consumer warps: 16x72 warp tile (M=128 oc, N=72 = 8 batches), K=128
//   4 producer warps: LDG (batched, MLP~36) -> cvt.rna.tf32 -> STS, double-buffered half-K
// W staged once per CTA, reused over 16 tiles. grid=(9,32) -> 1 wave @ 2 CTA/SM.

#define KK     9
#define CIN    128
#define COUT   128
#define NB     8
#define TILES  16
#define NTHR   384
#define NCONS  256          // consumer threads (warps 0..7)

#define SWS 132             // sW stride: A-frag banks (4g+t) perfect
#define SXS 72              // half-buffer stride: B-frag banks (8t+8nt+g) perfect
#define XH_WORDS (64 * SXS)             // 4608 words per half (18432 B)
#define SW_BYTES (128 * SWS * 4)        // 67584
#define SMEM_BYTES (SW_BYTES + 2 * XH_WORDS * 4)   // 104448 -> 2 CTAs/SM

// named barriers: full[h] = 1+h, empty[h] = 3+h
#define BAR_ARRIVE(id) asm volatile("bar.arrive %0, %1;" :: "r"(id), "r"(NTHR) : "memory")
#define BAR_SYNC(id)   asm volatile("bar.sync %0, %1;"   :: "r"(id), "r"(NTHR) : "memory")

__device__ __forceinline__ uint32_t f2tf32(float f) {
    uint32_t u;
    asm("cvt.rna.tf32.f32 %0, %1;" : "=r"(u) : "f"(f));
    return u;
}

__device__ __forceinline__ void mma_tf32(float* d, const uint32_t* a, const uint32_t* b) {
    asm volatile(
        "mma.sync.aligned.m16n8k8.row.col.f32.tf32.tf32.f32 "
        "{%0,%1,%2,%3}, {%4,%5,%6,%7}, {%8,%9}, {%0,%1,%2,%3};"
        : "+f"(d[0]), "+f"(d[1]), "+f"(d[2]), "+f"(d[3])
        : "r"(a[0]), "r"(a[1]), "r"(a[2]), "r"(a[3]), "r"(b[0]), "r"(b[1]));
}

__global__ void __launch_bounds__(NTHR, 2)
gather_vertical_ws(const float* __restrict__ in,
                   const float* __restrict__ w,
                   const float* __restrict__ bias,
                   float* __restrict__ out)
{
    extern __shared__ char smem[];
    uint32_t* sW = reinterpret_cast<uint32_t*>(smem);             // [oc][ci], stride SWS
    uint32_t* sX = reinterpret_cast<uint32_t*>(smem + SW_BYTES);  // two halves [64][72]

    const int tid = threadIdx.x;
    const int k   = blockIdx.x;
    const int yid = blockIdx.y;
    const int bbase = yid * TILES * NB;              // first batch of this CTA

    // ---- stage W[k] once (all 384 threads) ----
    {
        const float* wk = w + k * COUT * CIN;
        #pragma unroll 4
        for (int i = tid; i < COUT * CIN; i += NTHR) {
            int oc = i >> 7, ci = i & 127;
            sW[oc * SWS + ci] = f2tf32(wk[i]);
        }
    }
    __syncthreads();

    if (tid >= NCONS) {
        // =================== PRODUCER (4 warps, 128 threads) ===================
        const int ptid = tid - NCONS;
        const float* src = in + (size_t)bbase * (CIN * 81) + (size_t)k * 9;

        // precompute per-element (smem word offset, gmem offset) — compile-time except ptid base
        for (int s = 0; s < 2 * TILES; s++) {
            const int h = s & 1;
            const int t = s >> 1;
            if (s >= 2) BAR_SYNC(3 + h);             // wait consumers done with buf h

            uint32_t* dst = sX + h * XH_WORDS;
            const float* st = src + (size_t)(t * NB) * (CIN * 81) + h * 64 * 81;

            // batched: all 36 LDG in flight (MLP ~36), then cvt+STS
            float v[36];
            #pragma unroll
            for (int j = 0; j < 36; j++) {
                int e  = ptid + 128 * j;             // 0..4607
                int q  = e / 9;                      // bl*64 + ci_l
                int x  = e - 9 * q;
                int bl = q >> 6;
                int ci = q & 63;
                v[j] = st[(size_t)(bl * CIN + ci) * 81 + x];
            }
            #pragma unroll
            for (int j = 0; j < 36; j++) {
                int e  = ptid + 128 * j;
                int q  = e / 9;
                int x  = e - 9 * q;
                int bl = q >> 6;
                int ci = q & 63;
                dst[ci * SXS + bl * 9 + x] = f2tf32(v[j]);
            }
            asm volatile("fence.acq_rel.cta;" ::: "memory");
            BAR_ARRIVE(1 + h);                       // signal buf h full
        }
    } else {
        // =================== CONSUMER (8 warps, 256 threads) ===================
        const int wid  = tid >> 5, lane = tid & 31;
        const int g    = lane >> 2, tl = lane & 3;
        const int oc0  = wid * 16;
        const int r0   = oc0 + g, r1 = r0 + 8;
        const float bv0 = bias[k * COUT + r0];
        const float bv1 = bias[k * COUT + r1];

        for (int t = 0; t < TILES; t++) {
            float d[9][4];
            #pragma unroll
            for (int nt = 0; nt < 9; nt++)
                #pragma unroll
                for (int j = 0; j < 4; j++) d[nt][j] = 0.0f;

            #pragma unroll
            for (int h = 0; h < 2; h++) {
                BAR_SYNC(1 + h);                     // wait buf h full

                const uint32_t* pa0 = sW + r0 * SWS + h * 64 + tl;
                const uint32_t* pa1 = sW + r1 * SWS + h * 64 + tl;
                const uint32_t* pb  = sX + h * XH_WORDS + tl * SXS + g;

                #pragma unroll
                for (int ks = 0; ks < 8; ks++) {
                    uint32_t a[4];
                    a[0] = pa0[0];
                    a[1] = pa1[0];
                    a[2] = pa0[4];
                    a[3] = pa1[4];

                    uint32_t b[9][2];
                    #pragma unroll
                    for (int nt = 0; nt < 9; nt++) {
                        b[nt][0] = pb[nt * 8];
                        b[nt][1] = pb[4 * SXS + nt * 8];
                    }
                    #pragma unroll
                    for (int nt = 0; nt < 9; nt++)
                        mma_tf32(d[nt], a, b[nt]);

                    pa0 += 8; pa1 += 8; pb += 8 * SXS;
                }
                BAR_ARRIVE(3 + h);                   // release buf h
            }

            // ---- epilogue: direct STG (overlaps next tile's producer fill) ----
            float* ob = out + ((size_t)(bbase + t * NB) * 9 + k) * 1152;
            #pragma unroll
            for (int nt = 0; nt < 9; nt++) {
                int n   = nt * 8 + 2 * tl;
                int b0q = n / 9,       x0 = n - 9 * b0q;
                int b1q = (n + 1) / 9, x1 = (n + 1) - 9 * b1q;
                float* c0 = ob + (size_t)b0q * 10368;
                float* c1 = ob + (size_t)b1q * 10368;
                c0[r0 * 9 + x0] = d[nt][0] + bv0;
                c1[r0 * 9 + x1] = d[nt][1] + bv0;
                c0[r1 * 9 + x0] = d[nt][2] + bv1;
                c1[r1 * 9 + x1] = d[nt][3] + bv1;
            }
        }
    }
}

extern "C" void kernel_launch(void* const* d_in, const int* in_sizes, int n_in,
                              void* d_out, int out_size)
{
    const float* in   = (const float*)d_in[0];
    const float* w    = (const float*)d_in[1];
    const float* bias = (const float*)d_in[2];
    float* out        = (float*)d_out;

    int B = in_sizes[0] / (CIN * 81);        // 4096

    cudaFuncSetAttribute(gather_vertical_ws,
                         cudaFuncAttributeMaxDynamicSharedMemorySize, SMEM_BYTES);

    dim3 grid(KK, B / (NB * TILES));         // (9, 32)
    gather_vertical_ws<<<grid, NTHR, SMEM_BYTES>>>(in, w, bias, out);
}